// round 16
// baseline (speedup 1.0000x reference)
#include <cuda_runtime.h>
#include <cuda_fp16.h>
#include <cstdint>

#define NNODES 50000
#define DFEAT  512
#define DHID   1024
#define NCOLS  2048

// ---------------- device scratch ----------------
__device__ __align__(16) __half g_uvh[(size_t)NNODES * NCOLS];   // node activations fp16 [N, 2048]
__device__ __align__(16) __half g_bh[(size_t)NCOLS * DFEAT];     // W1^T fp16 [2048][512]
__device__ __align__(16) __half g_w2h[DHID];                     // W2 fp16

__device__ __forceinline__ uint32_t smem_u32(const void* p) {
    uint32_t a;
    asm("{ .reg .u64 t; cvta.to.shared.u64 t, %1; cvt.u32.u64 %0, t; }" : "=r"(a) : "l"(p));
    return a;
}
__device__ __forceinline__ uint32_t h2_bits(__half2 h) {
    return *reinterpret_cast<uint32_t*>(&h);
}

#define LDSM_X4(r0, r1, r2, r3, a) \
    asm volatile("ldmatrix.sync.aligned.m8n8.x4.shared.b16 {%0,%1,%2,%3}, [%4];" \
                 : "=r"(r0), "=r"(r1), "=r"(r2), "=r"(r3) : "r"(a))

#define MMA_F16(d, a, b) \
    asm volatile("mma.sync.aligned.m16n8k16.row.col.f32.f16.f16.f32 " \
                 "{%0,%1,%2,%3}, {%4,%5,%6,%7}, {%8,%9}, {%0,%1,%2,%3};" \
                 : "+f"((d)[0]), "+f"((d)[1]), "+f"((d)[2]), "+f"((d)[3]) \
                 : "r"((a)[0]), "r"((a)[1]), "r"((a)[2]), "r"((a)[3]), "r"((b)[0]), "r"((b)[1]))

#define CP_ASYNC16(sa, ga, sz) \
    asm volatile("cp.async.cg.shared.global [%0], [%1], 16, %2;" :: "r"(sa), "l"(ga), "r"(sz))
#define CP_COMMIT() asm volatile("cp.async.commit_group;" ::: "memory")
#define CP_WAIT2()  asm volatile("cp.async.wait_group 2;" ::: "memory")
#define CP_WAIT0()  asm volatile("cp.async.wait_group 0;" ::: "memory")

// W1^T fp16:  g_bh[n][k] = W1[half(n)*512 + k][n & 1023];  also W2 -> fp16
__global__ __launch_bounds__(256)
void convert_w_kernel(const float* __restrict__ W1, const float* __restrict__ W2) {
    __shared__ float tile[32][33];
    const int k0 = blockIdx.x * 32;     // k in [0,512)
    const int n0 = blockIdx.y * 32;     // n in [0,2048)
    const int tx = threadIdx.x, ty = threadIdx.y;   // 32 x 8
    const int roff = (n0 >= DHID) ? DFEAT : 0;
#pragma unroll
    for (int j = 0; j < 32; j += 8) {
        int k = k0 + ty + j;
        int n = n0 + tx;
        tile[ty + j][tx] = W1[(size_t)(roff + k) * DHID + (n & (DHID - 1))];
    }
    __syncthreads();
#pragma unroll
    for (int j = 0; j < 32; j += 8) {
        int n = n0 + ty + j;
        int k = k0 + tx;
        g_bh[(size_t)n * DFEAT + k] = __float2half_rn(tile[tx][ty + j]);
    }
    if (blockIdx.y == 0) {
        int idx = blockIdx.x * 256 + ty * 32 + tx;
        if (idx < DHID && blockIdx.x < 4) g_w2h[idx] = __float2half_rn(W2[idx]);
    }
}

// ---------------- HMMA fp16 GEMM with fused X conversion:
//   g_uvh = fp16( X @ [W1_top|W1_bot] (+b1 on u-half) )
// A path: fp32 LDG -> reg convert -> fp16 STS (double-buffered tile, 1-kt lookahead)
// B path: cp.async 4-stage from g_bh (unchanged).
#define BM 128
#define BN 128
#define BK 32
#define PITCH 80                        // 5 x 16B: conflict-free ldmatrix, no swizzle
#define TILE_B (128 * PITCH)            // 10240 B
#define OFF_B  (2 * TILE_B)             // A double-buffer in [0, 2*TILE_B)
#define NSTAGE_B 4
#define SMEM_DYN (OFF_B + NSTAGE_B * TILE_B)   // 61440 B

__global__ __launch_bounds__(256, 2)
void gemm_mma_kernel(const float* __restrict__ X, const float* __restrict__ b1) {
    extern __shared__ char smem[];
    const uint32_t sbase = smem_u32(smem);
    const int tid = threadIdx.x;
    const int wid = tid >> 5, lane = tid & 31;
    const int col0 = blockIdx.x * BN;
    const int row0 = blockIdx.y * BM;
    const int warp_m = wid & 3;         // 4 m-warps of 32 rows
    const int warp_n = wid >> 2;        // 2 n-warps of 64 cols

    float acc[2][8][4];
#pragma unroll
    for (int mi = 0; mi < 2; mi++)
#pragma unroll
        for (int ni = 0; ni < 8; ni++)
#pragma unroll
            for (int q = 0; q < 4; q++) acc[mi][ni][q] = 0.f;

    // ---- A-side: thread t handles row ar = t>>1, k-halfchunk ak = (t&1)*16
    const int ar = tid >> 1;
    const int ak = (tid & 1) * 16;
    const bool arow_ok = (row0 + ar < NNODES);
    const float* __restrict__ Abase = X + (size_t)(row0 + ar) * DFEAT + ak;
    float4 areg[4];
    auto ldg_a = [&](int kt) {
        const float4* p = (const float4*)(Abase + kt * BK);
#pragma unroll
        for (int i = 0; i < 4; i++)
            areg[i] = arow_ok ? __ldg(p + i) : make_float4(0.f, 0.f, 0.f, 0.f);
    };
    const uint32_t a_sts = sbase + (uint32_t)(ar * PITCH + ak * 2);
    auto sts_a = [&](int buf) {
        uint32_t h[8];
#pragma unroll
        for (int i = 0; i < 4; i++) {
            h[2 * i]     = h2_bits(__floats2half2_rn(areg[i].x, areg[i].y));
            h[2 * i + 1] = h2_bits(__floats2half2_rn(areg[i].z, areg[i].w));
        }
        uint32_t dst = a_sts + buf * TILE_B;
        asm volatile("st.shared.v4.b32 [%0], {%1,%2,%3,%4};" :: "r"(dst),
                     "r"(h[0]), "r"(h[1]), "r"(h[2]), "r"(h[3]));
        asm volatile("st.shared.v4.b32 [%0], {%1,%2,%3,%4};" :: "r"(dst + 16),
                     "r"(h[4]), "r"(h[5]), "r"(h[6]), "r"(h[7]));
    };

    // ---- B-side stage fill (cp.async): rows lr, lr+64 of the 128-col tile
    const int lr  = tid >> 2;           // 0..63
    const int lc4 = tid & 3;
    auto issue_b = [&](int kt, int slot) {
        const int k0 = kt * BK;
        const uint32_t sb = sbase + OFF_B + slot * TILE_B;
#pragma unroll
        for (int h = 0; h < 2; h++) {
            const int r = lr + h * 64;
            const uint32_t so = (uint32_t)(r * PITCH + lc4 * 16);
            const size_t boff = (size_t)(col0 + r) * DFEAT + k0 + lc4 * 8;
            CP_ASYNC16(sb + so, g_bh + boff, 16);
        }
        CP_COMMIT();
    };

    const uint32_t a_off = (uint32_t)((warp_m * 32 + (lane & 15)) * PITCH + (lane >> 4) * 16);
    const int grp = lane >> 3, r8 = lane & 7;
    const uint32_t b_off = (uint32_t)((warp_n * 64 + ((grp & 2) ? 8 : 0) + r8) * PITCH
                                      + ((grp & 1) ? 16 : 0));

    ldg_a(0);
    issue_b(0, 0);
    issue_b(1, 1);
    issue_b(2, 2);

    const int KT = DFEAT / BK;          // 16
    for (int kt = 0; kt < KT; kt++) {
        if (kt + 3 < KT) CP_WAIT2(); else CP_WAIT0();
        sts_a(kt & 1);                  // convert+store this kt's A tile
        __syncthreads();
        if (kt + 3 < KT) issue_b(kt + 3, (kt + 3) % NSTAGE_B);
        if (kt + 1 < KT) ldg_a(kt + 1); // prefetch next A (lands during MMA block)

        const uint32_t sa = sbase + (kt & 1) * TILE_B;
        const uint32_t sb = sbase + OFF_B + (kt % NSTAGE_B) * TILE_B;
#pragma unroll
        for (int ks = 0; ks < 2; ks++) {
            const uint32_t kb = ks * 32;
            uint32_t ah[2][4], bh[8][2];
#pragma unroll
            for (int mi = 0; mi < 2; mi++) {
                uint32_t aa = sa + a_off + mi * (16 * PITCH) + kb;
                LDSM_X4(ah[mi][0], ah[mi][1], ah[mi][2], ah[mi][3], aa);
            }
#pragma unroll
            for (int p = 0; p < 4; p++) {
                uint32_t ba = sb + b_off + p * (16 * PITCH) + kb;
                LDSM_X4(bh[2 * p][0], bh[2 * p][1], bh[2 * p + 1][0], bh[2 * p + 1][1], ba);
            }
#pragma unroll
            for (int mi = 0; mi < 2; mi++)
#pragma unroll
                for (int ni = 0; ni < 8; ni++)
                    MMA_F16(acc[mi][ni], ah[mi], bh[ni]);
        }
        __syncthreads();
    }

    // --- epilogue: add b1 to u-half, convert to fp16, write g_uvh
    const int r_lo = lane >> 2;
    const int c_lo = (lane & 3) * 2;
#pragma unroll
    for (int mi = 0; mi < 2; mi++) {
        const int row_a = row0 + warp_m * 32 + mi * 16 + r_lo;
        const int row_b = row_a + 8;
#pragma unroll
        for (int ni = 0; ni < 8; ni++) {
            const int col = col0 + warp_n * 64 + ni * 8 + c_lo;
            float bx = 0.f, by = 0.f;
            if (col < DHID) { bx = __ldg(b1 + col); by = __ldg(b1 + col + 1); }
            if (row_a < NNODES)
                *(__half2*)(g_uvh + (size_t)row_a * NCOLS + col) =
                    __floats2half2_rn(acc[mi][ni][0] + bx, acc[mi][ni][1] + by);
            if (row_b < NNODES)
                *(__half2*)(g_uvh + (size_t)row_b * NCOLS + col) =
                    __floats2half2_rn(acc[mi][ni][2] + bx, acc[mi][ni][3] + by);
        }
    }
}

// ---------------- per-edge: out[e] = relu(u'[src] + v[dst]) . W2 + b2  (b1 folded into u')
// One warp per edge, half2 relu math, fp32 accumulation. (R13 version, unchanged.)
__global__ __launch_bounds__(256)
void edge_kernel(const int* __restrict__ src32, const int* __restrict__ dst32,
                 const float* __restrict__ b2, float* __restrict__ out, int E) {
    __shared__ int s_is64;
    if (threadIdx.x == 0) {
        int orv = 0;
#pragma unroll
        for (int i = 1; i < 16; i += 2) orv |= src32[i] | dst32[i];
        s_is64 = (orv == 0) ? 1 : 0;
    }
    __syncthreads();

    const int wid  = threadIdx.x >> 5;
    const int lane = threadIdx.x & 31;
    const int e = blockIdx.x * 8 + wid;
    if (e >= E) return;

    const int sh = s_is64;
    const int s = src32[(size_t)e << sh];
    const int d = dst32[(size_t)e << sh];

    const uint4* __restrict__ U = (const uint4*)(g_uvh + (size_t)s * NCOLS);
    const uint4* __restrict__ V = (const uint4*)(g_uvh + (size_t)d * NCOLS + DHID);
    const uint4* __restrict__ W = (const uint4*)g_w2h;

    const __half2 z2 = __float2half2_rn(0.f);
    float acc = 0.f;
#pragma unroll
    for (int i = 0; i < 4; i++) {
        const int c = i * 32 + lane;        // uint4 index: 8 halves
        uint4 u = U[c];
        uint4 v = V[c];
        uint4 w = W[c];
        const __half2* uh = (const __half2*)&u;
        const __half2* vh = (const __half2*)&v;
        const __half2* wh = (const __half2*)&w;
#pragma unroll
        for (int j = 0; j < 4; j++) {
            __half2 h = __hmax2(__hadd2(uh[j], vh[j]), z2);   // relu(u+v) in fp16
            float2 hf = __half22float2(h);
            float2 wf = __half22float2(wh[j]);
            acc = fmaf(hf.x, wf.x, acc);
            acc = fmaf(hf.y, wf.y, acc);
        }
    }
#pragma unroll
    for (int o = 16; o > 0; o >>= 1) acc += __shfl_xor_sync(0xffffffffu, acc, o);
    if (lane == 0) out[e] = acc + __ldg(b2);
}

extern "C" void kernel_launch(void* const* d_in, const int* in_sizes, int n_in,
                              void* d_out, int out_size) {
    const float* x   = (const float*)d_in[0];
    const int*   src = (const int*)d_in[1];
    const int*   dst = (const int*)d_in[2];
    const float* W1  = (const float*)d_in[3];
    const float* b1  = (const float*)d_in[4];
    const float* W2  = (const float*)d_in[5];
    const float* b2  = (const float*)d_in[6];
    float* out = (float*)d_out;
    const int E = in_sizes[1];

    cudaFuncSetAttribute(gemm_mma_kernel, cudaFuncAttributeMaxDynamicSharedMemorySize, SMEM_DYN);

    convert_w_kernel<<<dim3(DFEAT / 32, NCOLS / 32), dim3(32, 8)>>>(W1, W2);
    gemm_mma_kernel<<<dim3(NCOLS / BN, (NNODES + BM - 1) / BM), 256, SMEM_DYN>>>(x, b1);
    edge_kernel<<<(E + 7) / 8, 256>>>(src, dst, b2, out, E);
}